// round 4
// baseline (speedup 1.0000x reference)
#include <cuda_runtime.h>

// Problem constants
#define S_DIM 5
#define B_DIM 16
#define C_DIM 11
#define H_DIM 128
#define W_DIM 128
#define SLICE   (C_DIM * H_DIM * W_DIM)   // 180224 floats per (s,b)
#define SLICE4  (SLICE / 4)               // 45056 float4 per (s,b)
#define NSLICE  (S_DIM * B_DIM)           // 80
#define BLOCKS_PER_SLICE 14               // 1120 blocks: 94.6% warp fill, 1 wave
#define THREADS 256
#define STRIDE  (BLOCKS_PER_SLICE * THREADS)  // 3584
#define FULL_ITERS 12                     // 12*3584 = 43008; remainder 2048
#define NCLASS 11
#define F_DIM 7
#define LBL (NCLASS * F_DIM)              // 77

// Scratch (no cudaMalloc allowed). g_count zero-initialized at load; reset to
// 0 in the epilogue every launch -> deterministic across graph replays.
__device__ float g_partial[NSLICE * BLOCKS_PER_SLICE];
__device__ int   g_count[NSLICE];

__global__ void __launch_bounds__(THREADS, 8)
keypoint_loss_kernel(const float4* __restrict__ hp,
                     const float4* __restrict__ hm,
                     const float*  __restrict__ label_preds,
                     const float*  __restrict__ labels,
                     float* __restrict__ out) {
    const int p = blockIdx.y;  // slice = s*B + b
    const float4* __restrict__ a = hp + (size_t)p * SLICE4;
    const float4* __restrict__ bb = hm + (size_t)p * SLICE4;

    const int base = blockIdx.x * THREADS + threadIdx.x;  // 0..3583

    float s0 = 0.0f, s1 = 0.0f, s2 = 0.0f, s3 = 0.0f;

    #pragma unroll
    for (int k = 0; k < FULL_ITERS; k++) {
        int idx = base + k * STRIDE;
        float4 x = __ldcs(&a[idx]);
        float4 y = __ldcs(&bb[idx]);
        float d0 = x.x - y.x;
        float d1 = x.y - y.y;
        float d2 = x.z - y.z;
        float d3 = x.w - y.w;
        s0 += d0 * d0;
        s1 += d1 * d1;
        s2 += d2 * d2;
        s3 += d3 * d3;
    }
    // Remainder: 2048 float4 -> exactly blocks 0..7 of each slice (uniform
    // per-block branch; base < 2048 iff blockIdx.x < 8).
    if (base < SLICE4 - FULL_ITERS * STRIDE) {
        int idx = base + FULL_ITERS * STRIDE;
        float4 x = __ldcs(&a[idx]);
        float4 y = __ldcs(&bb[idx]);
        float d0 = x.x - y.x;
        float d1 = x.y - y.y;
        float d2 = x.z - y.z;
        float d3 = x.w - y.w;
        s0 += d0 * d0;
        s1 += d1 * d1;
        s2 += d2 * d2;
        s3 += d3 * d3;
    }
    float sum = (s0 + s1) + (s2 + s3);

    // block reduce
    #pragma unroll
    for (int o = 16; o > 0; o >>= 1)
        sum += __shfl_down_sync(0xffffffffu, sum, o);

    __shared__ float ws[THREADS / 32];
    __shared__ int s_last;
    if ((threadIdx.x & 31) == 0) ws[threadIdx.x >> 5] = sum;
    __syncthreads();

    if (threadIdx.x == 0) {
        float v = 0.0f;
        #pragma unroll
        for (int i = 0; i < THREADS / 32; i++) v += ws[i];
        g_partial[p * BLOCKS_PER_SLICE + blockIdx.x] = v;
        // Release-acquire counter bump: orders the partial store before the
        // increment WITHOUT a gpu-scope fence (no CCTL.IVALL / L1 flush).
        int prev;
        asm volatile("atom.acq_rel.gpu.global.add.s32 %0, [%1], 1;"
                     : "=r"(prev)
                     : "l"(&g_count[p])
                     : "memory");
        s_last = (prev == BLOCKS_PER_SLICE - 1) ? 1 : 0;
    }
    __syncthreads();

    if (!s_last) return;

    // ---- epilogue: last-arriving block of this slice finalizes ----
    const int s = p / B_DIM;
    const int b = p % B_DIM;
    const int tid = threadIdx.x;

    // Label loss: 77 squared diffs, block-reduced (threads 0..76 active)
    float lsum = 0.0f;
    if (tid < LBL) {
        float d = label_preds[(size_t)p * LBL + tid] - labels[b * LBL + tid];
        lsum = d * d;
    }
    #pragma unroll
    for (int o = 16; o > 0; o >>= 1)
        lsum += __shfl_down_sync(0xffffffffu, lsum, o);

    if ((tid & 31) == 0) ws[tid >> 5] = lsum;  // reuse ws (post-syncthreads)
    __syncthreads();

    if (tid == 0) {
        // labels_loss [B, S] (warps 3..7 contributed 0)
        out[NSLICE + b * S_DIM + s] = ws[0] + ws[1] + ws[2];

        // combined_loss [B, S]: fold partials in fixed order, L2-direct loads
        float h = 0.0f;
        #pragma unroll
        for (int i = 0; i < BLOCKS_PER_SLICE; i++)
            h += __ldcg(&g_partial[p * BLOCKS_PER_SLICE + i]);
        out[b * S_DIM + s] = h * (1.0f / (float)(H_DIM * W_DIM));

        // reset counter for next graph replay
        g_count[p] = 0;
    }
}

extern "C" void kernel_launch(void* const* d_in, const int* in_sizes, int n_in,
                              void* d_out, int out_size) {
    const float4* hp = (const float4*)d_in[0];   // heat_preds  [5,16,11,128,128]
    const float4* hm = (const float4*)d_in[1];   // heatmaps    [5,16,11,128,128]
    const float*  lp = (const float*)d_in[2];    // label_preds [5,16,11,7]
    const float*  lb = (const float*)d_in[3];    // labels      [16,11,7]
    float* out = (float*)d_out;                  // 160 floats: combined | labels_loss

    dim3 grid(BLOCKS_PER_SLICE, NSLICE);
    keypoint_loss_kernel<<<grid, THREADS>>>(hp, hm, lp, lb, out);
}

// round 5
// speedup vs baseline: 1.0473x; 1.0473x over previous
#include <cuda_runtime.h>

// Problem constants
#define S_DIM 5
#define B_DIM 16
#define C_DIM 11
#define H_DIM 128
#define W_DIM 128
#define SLICE   (C_DIM * H_DIM * W_DIM)   // 180224 floats per (s,b)
#define SLICE4  (SLICE / 4)               // 45056 float4 per (s,b)
#define NSLICE  (S_DIM * B_DIM)           // 80
#define BLOCKS_PER_SLICE 14               // 1120 blocks: 94.6% warp fill, 1 wave
#define THREADS 256
#define STRIDE  (BLOCKS_PER_SLICE * THREADS)  // 3584
#define FULL_ITERS 12                     // 12*3584 = 43008; remainder 2048
#define NCLASS 11
#define F_DIM 7
#define LBL (NCLASS * F_DIM)              // 77

// Scratch (no cudaMalloc allowed). g_count zero-initialized at load; reset to
// 0 in the epilogue every launch -> deterministic across graph replays.
__device__ float g_partial[NSLICE * BLOCKS_PER_SLICE];
__device__ int   g_count[NSLICE];

__global__ void __launch_bounds__(THREADS, 8)
keypoint_loss_kernel(const float4* __restrict__ hp,
                     const float4* __restrict__ hm,
                     const float*  __restrict__ label_preds,
                     const float*  __restrict__ labels,
                     float* __restrict__ out) {
    const int p = blockIdx.y;  // slice = s*B + b
    const float4* __restrict__ a = hp + (size_t)p * SLICE4;
    const float4* __restrict__ bb = hm + (size_t)p * SLICE4;

    const int base = blockIdx.x * THREADS + threadIdx.x;  // 0..3583

    float s0 = 0.0f, s1 = 0.0f, s2 = 0.0f, s3 = 0.0f;

    // Default cached loads: inputs (115.4 MB) nearly fit in the 126 MB L2,
    // so graph replays re-hit L2. (__ldcs evict-first defeated this.)
    #pragma unroll
    for (int k = 0; k < FULL_ITERS; k++) {
        int idx = base + k * STRIDE;
        float4 x = a[idx];
        float4 y = bb[idx];
        float d0 = x.x - y.x;
        float d1 = x.y - y.y;
        float d2 = x.z - y.z;
        float d3 = x.w - y.w;
        s0 += d0 * d0;
        s1 += d1 * d1;
        s2 += d2 * d2;
        s3 += d3 * d3;
    }
    // Remainder: 2048 float4 -> exactly blocks 0..7 of each slice (uniform
    // per-block branch; base < 2048 iff blockIdx.x < 8).
    if (base < SLICE4 - FULL_ITERS * STRIDE) {
        int idx = base + FULL_ITERS * STRIDE;
        float4 x = a[idx];
        float4 y = bb[idx];
        float d0 = x.x - y.x;
        float d1 = x.y - y.y;
        float d2 = x.z - y.z;
        float d3 = x.w - y.w;
        s0 += d0 * d0;
        s1 += d1 * d1;
        s2 += d2 * d2;
        s3 += d3 * d3;
    }
    float sum = (s0 + s1) + (s2 + s3);

    // block reduce
    #pragma unroll
    for (int o = 16; o > 0; o >>= 1)
        sum += __shfl_down_sync(0xffffffffu, sum, o);

    __shared__ float ws[THREADS / 32];
    __shared__ int s_last;
    if ((threadIdx.x & 31) == 0) ws[threadIdx.x >> 5] = sum;
    __syncthreads();

    if (threadIdx.x == 0) {
        float v = 0.0f;
        #pragma unroll
        for (int i = 0; i < THREADS / 32; i++) v += ws[i];
        g_partial[p * BLOCKS_PER_SLICE + blockIdx.x] = v;
        // Release-acquire counter bump: orders the partial store before the
        // increment WITHOUT a gpu-scope fence (no CCTL.IVALL / L1 flush).
        int prev;
        asm volatile("atom.acq_rel.gpu.global.add.s32 %0, [%1], 1;"
                     : "=r"(prev)
                     : "l"(&g_count[p])
                     : "memory");
        s_last = (prev == BLOCKS_PER_SLICE - 1) ? 1 : 0;
    }
    __syncthreads();

    if (!s_last) return;

    // ---- epilogue: last-arriving block of this slice finalizes ----
    const int s = p / B_DIM;
    const int b = p % B_DIM;
    const int tid = threadIdx.x;

    // Label loss: 77 squared diffs, block-reduced (threads 0..76 active)
    float lsum = 0.0f;
    if (tid < LBL) {
        float d = label_preds[(size_t)p * LBL + tid] - labels[b * LBL + tid];
        lsum = d * d;
    }
    #pragma unroll
    for (int o = 16; o > 0; o >>= 1)
        lsum += __shfl_down_sync(0xffffffffu, lsum, o);

    if ((tid & 31) == 0) ws[tid >> 5] = lsum;  // reuse ws (post-syncthreads)
    __syncthreads();

    if (tid == 0) {
        // labels_loss [B, S] (warps 3..7 contributed 0)
        out[NSLICE + b * S_DIM + s] = ws[0] + ws[1] + ws[2];

        // combined_loss [B, S]: fold partials in fixed order, L2-direct loads
        float h = 0.0f;
        #pragma unroll
        for (int i = 0; i < BLOCKS_PER_SLICE; i++)
            h += __ldcg(&g_partial[p * BLOCKS_PER_SLICE + i]);
        out[b * S_DIM + s] = h * (1.0f / (float)(H_DIM * W_DIM));

        // reset counter for next graph replay
        g_count[p] = 0;
    }
}

extern "C" void kernel_launch(void* const* d_in, const int* in_sizes, int n_in,
                              void* d_out, int out_size) {
    const float4* hp = (const float4*)d_in[0];   // heat_preds  [5,16,11,128,128]
    const float4* hm = (const float4*)d_in[1];   // heatmaps    [5,16,11,128,128]
    const float*  lp = (const float*)d_in[2];    // label_preds [5,16,11,7]
    const float*  lb = (const float*)d_in[3];    // labels      [16,11,7]
    float* out = (float*)d_out;                  // 160 floats: combined | labels_loss

    dim3 grid(BLOCKS_PER_SLICE, NSLICE);
    keypoint_loss_kernel<<<grid, THREADS>>>(hp, hm, lp, lb, out);
}